// round 13
// baseline (speedup 1.0000x reference)
#include <cuda_runtime.h>
#include <cuda_fp16.h>
#include <cstdint>

#define N_NODES 50000
#define N_EDGES 800000
#define F_IN    128
#define HID     64
#define HEADS   4
#define L1_OUT  (HEADS*HID)   // 256
#define CLASSES 40
#define NEG_SLOPE 0.2f
#define EPS 1e-16f
#define CAP   96               // bucket capacity per dst (Poisson(16); P(>=96)~e-60)

#define GEMM1_TILES 391            // ceil(50000/128)
#define SCAT_BLOCKS 1563           // ceil(800000 / (256*2))
#define PREP_BLOCKS 782            // 200000 detect threads / 256

#define SPLIT_NODE  25088          // 196 * 128 — agg1/gemm2 pipeline split
#define G2_TILES_A  196
#define G2_TILES_B  195
#define AGG1_BLK_A  3136           // 25088 warps / 8
#define AGG1_BLK_B  3114           // ceil(24912 / 8)

// ---------------- scratch --------------------------------------------------
__device__ __align__(16) __half g_h1h [(size_t)N_NODES * L1_OUT];
__device__ __align__(16) __half g_out1h[(size_t)N_NODES * L1_OUT];
__device__ __align__(16) __half g_h2h [(size_t)N_NODES * CLASSES];
__device__ __align__(16) float g_as1[N_NODES * HEADS];
__device__ __align__(16) float g_ad1[N_NODES * HEADS];
__device__ float g_as2[N_NODES];
__device__ float g_ad2[N_NODES];
__device__ int   g_cnt[N_NODES];
__device__ int   g_ssrc[(size_t)N_NODES * CAP];
__device__ int   g_idx_bad;        // 0 between launches; set by prep, reset by agg1

// ---------------- helpers ---------------------------------------------------
__device__ __forceinline__ float warpMax(float v) {
#pragma unroll
    for (int s = 16; s > 0; s >>= 1)
        v = fmaxf(v, __shfl_xor_sync(0xffffffffu, v, s));
    return v;
}
__device__ __forceinline__ float warpSum(float v) {
#pragma unroll
    for (int s = 16; s > 0; s >>= 1)
        v += __shfl_xor_sync(0xffffffffu, v, s);
    return v;
}
__device__ __forceinline__ float lrelu(float x) {
    return (x > 0.f) ? x : NEG_SLOPE * x;
}
__device__ __forceinline__ uint32_t smem_u32(const void* p) {
    return (uint32_t)__cvta_generic_to_shared(p);
}
__device__ __forceinline__ void ldmatrix_x4(uint32_t* r, uint32_t addr) {
    asm volatile("ldmatrix.sync.aligned.m8n8.x4.shared.b16 {%0,%1,%2,%3}, [%4];"
                 : "=r"(r[0]), "=r"(r[1]), "=r"(r[2]), "=r"(r[3]) : "r"(addr));
}
__device__ __forceinline__ void ldmatrix_x4_trans(uint32_t* r, uint32_t addr) {
    asm volatile("ldmatrix.sync.aligned.m8n8.x4.trans.shared.b16 {%0,%1,%2,%3}, [%4];"
                 : "=r"(r[0]), "=r"(r[1]), "=r"(r[2]), "=r"(r[3]) : "r"(addr));
}
__device__ __forceinline__ void ldmatrix_x2_trans(uint32_t* r, uint32_t addr) {
    asm volatile("ldmatrix.sync.aligned.m8n8.x2.trans.shared.b16 {%0,%1}, [%2];"
                 : "=r"(r[0]), "=r"(r[1]) : "r"(addr));
}
__device__ __forceinline__ void mma16816(float* c, const uint32_t* a, const uint32_t* b) {
    asm volatile(
        "mma.sync.aligned.m16n8k16.row.col.f32.f16.f16.f32 "
        "{%0,%1,%2,%3}, {%4,%5,%6,%7}, {%8,%9}, {%0,%1,%2,%3};"
        : "+f"(c[0]), "+f"(c[1]), "+f"(c[2]), "+f"(c[3])
        : "r"(a[0]), "r"(a[1]), "r"(a[2]), "r"(a[3]), "r"(b[0]), "r"(b[1]));
}

// ---------------- prep: zero counts + sampled dtype detection ----------------
__global__ void prep_kernel(const long long* __restrict__ ei) {
    int i = blockIdx.x * blockDim.x + threadIdx.x;
    if (i < N_NODES) g_cnt[i] = 0;
    int e = i * 4;
    if (e < N_EDGES) {
        long long v = __ldg(ei + e);
        if (v < 0 || v >= N_NODES) g_idx_bad = 1;
    }
}

// ---------------- bucket scatter (2 edges/thread) -----------------------------
__global__ void scatter_kernel(const void* __restrict__ eiv) {
    int e0 = (blockIdx.x * 256 + threadIdx.x) * 2;
    if (e0 >= N_EDGES) return;
    int s0, s1, d0, d1;
    if (!g_idx_bad) {
        longlong2 a = __ldg((const longlong2*)((const long long*)eiv + e0));
        longlong2 d = __ldg((const longlong2*)((const long long*)eiv + N_EDGES + e0));
        s0 = (int)a.x; s1 = (int)a.y; d0 = (int)d.x; d1 = (int)d.y;
    } else {
        int2 a = __ldg((const int2*)((const int*)eiv + e0));
        int2 d = __ldg((const int2*)((const int*)eiv + N_EDGES + e0));
        s0 = a.x; s1 = a.y; d0 = d.x; d1 = d.y;
    }
    int p0 = atomicAdd(&g_cnt[d0], 1);
    if (p0 < CAP) g_ssrc[(size_t)d0 * CAP + p0] = s0;
    int p1 = atomicAdd(&g_cnt[d1], 1);
    if (p1 < CAP) g_ssrc[(size_t)d1 * CAP + p1] = s1;
}

// ---------------- GEMM1 via HMMA (unchanged) ----------------------------------
#define APAD 40
#define BPAD 264
__global__ __launch_bounds__(256) void kGemm1(
    const float* __restrict__ A, const float* __restrict__ B,
    const float* __restrict__ a_src, const float* __restrict__ a_dst)
{
    __shared__ __half smem[128 * APAD + 32 * BPAD];
    __half* As = smem;                 // [128][APAD]
    __half* Bs = smem + 128 * APAD;    // [32][BPAD]
    const int tid = threadIdx.x;
    const int wid = tid >> 5, lane = tid & 31;
    const int bm = blockIdx.x * 128;
    const int wm = (wid >> 2) * 64;
    const int wn = (wid & 3) * 64;
    const int head = wid & 3;

    const int ar = tid >> 1;
    const int ac = (tid & 1) * 16;
    const int br = tid >> 3;
    const int bc = (tid & 7) * 32;

    const float* Ap = A + (size_t)(bm + ar) * F_IN + ac;
    const bool aval = (bm + ar) < N_NODES;
    const float* Bp = B + (size_t)br * L1_OUT + bc;
    const float4 z = make_float4(0.f, 0.f, 0.f, 0.f);

    float acc[4][8][4];
#pragma unroll
    for (int i = 0; i < 4; i++)
#pragma unroll
        for (int j = 0; j < 8; j++)
#pragma unroll
            for (int q = 0; q < 4; q++) acc[i][j][q] = 0.f;

    float4 ra[4], rb[8];
#pragma unroll
    for (int q = 0; q < 4; q++) ra[q] = aval ? __ldg((const float4*)(Ap + q * 4)) : z;
#pragma unroll
    for (int q = 0; q < 8; q++) rb[q] = __ldg((const float4*)(Bp + q * 4));

    uint32_t a_addr[4], b_addr[4];
#pragma unroll
    for (int mi = 0; mi < 4; mi++)
        a_addr[mi] = smem_u32(As + (wm + mi * 16 + (lane & 15)) * APAD + (lane >> 4) * 8);
#pragma unroll
    for (int nj = 0; nj < 4; nj++)
        b_addr[nj] = smem_u32(Bs + (lane & 15) * BPAD + wn + nj * 16 + (lane >> 4) * 8);

    for (int kk = 0; kk < F_IN / 32; kk++) {
        if (kk > 0) __syncthreads();
        {
            __half2* Arow = (__half2*)(As + ar * APAD + ac);
#pragma unroll
            for (int q = 0; q < 4; q++) {
                Arow[q * 2]     = __floats2half2_rn(ra[q].x, ra[q].y);
                Arow[q * 2 + 1] = __floats2half2_rn(ra[q].z, ra[q].w);
            }
            __half2* Brow = (__half2*)(Bs + br * BPAD + bc);
#pragma unroll
            for (int q = 0; q < 8; q++) {
                Brow[q * 2]     = __floats2half2_rn(rb[q].x, rb[q].y);
                Brow[q * 2 + 1] = __floats2half2_rn(rb[q].z, rb[q].w);
            }
        }
        __syncthreads();
        if (kk < F_IN / 32 - 1) {
            int k0 = (kk + 1) * 32;
#pragma unroll
            for (int q = 0; q < 4; q++)
                ra[q] = aval ? __ldg((const float4*)(Ap + k0 + q * 4)) : z;
#pragma unroll
            for (int q = 0; q < 8; q++)
                rb[q] = __ldg((const float4*)(Bp + (size_t)k0 * L1_OUT + q * 4));
        }
#pragma unroll
        for (int k16 = 0; k16 < 2; k16++) {
            uint32_t af[4][4], bf[8][2];
#pragma unroll
            for (int mi = 0; mi < 4; mi++)
                ldmatrix_x4(af[mi], a_addr[mi] + k16 * 32);
#pragma unroll
            for (int nj = 0; nj < 4; nj++) {
                uint32_t t[4];
                ldmatrix_x4_trans(t, b_addr[nj] + k16 * 16 * BPAD * 2);
                bf[nj * 2][0] = t[0]; bf[nj * 2][1] = t[1];
                bf[nj * 2 + 1][0] = t[2]; bf[nj * 2 + 1][1] = t[3];
            }
#pragma unroll
            for (int mi = 0; mi < 4; mi++)
#pragma unroll
                for (int ni = 0; ni < 8; ni++)
                    mma16816(acc[mi][ni], af[mi], bf[ni]);
        }
    }

    float as0[8], as1[8], ad0[8], ad1[8];
    int cb = (lane & 3) * 2;
#pragma unroll
    for (int ni = 0; ni < 8; ni++) {
        int col = wn + ni * 8 + cb;
        as0[ni] = __ldg(a_src + col); as1[ni] = __ldg(a_src + col + 1);
        ad0[ni] = __ldg(a_dst + col); ad1[ni] = __ldg(a_dst + col + 1);
    }
#pragma unroll
    for (int mi = 0; mi < 4; mi++) {
        float sl = 0.f, sh = 0.f, dl = 0.f, dh = 0.f;
#pragma unroll
        for (int ni = 0; ni < 8; ni++) {
            sl = fmaf(acc[mi][ni][0], as0[ni], fmaf(acc[mi][ni][1], as1[ni], sl));
            sh = fmaf(acc[mi][ni][2], as0[ni], fmaf(acc[mi][ni][3], as1[ni], sh));
            dl = fmaf(acc[mi][ni][0], ad0[ni], fmaf(acc[mi][ni][1], ad1[ni], dl));
            dh = fmaf(acc[mi][ni][2], ad0[ni], fmaf(acc[mi][ni][3], ad1[ni], dh));
        }
#pragma unroll
        for (int s = 1; s < 4; s <<= 1) {
            sl += __shfl_xor_sync(0xffffffffu, sl, s);
            sh += __shfl_xor_sync(0xffffffffu, sh, s);
            dl += __shfl_xor_sync(0xffffffffu, dl, s);
            dh += __shfl_xor_sync(0xffffffffu, dh, s);
        }
        int row_lo = bm + wm + mi * 16 + (lane >> 2);
        int row_hi = row_lo + 8;
        if ((lane & 3) == 0) {
            if (row_lo < N_NODES) { g_as1[row_lo * 4 + head] = sl; g_ad1[row_lo * 4 + head] = dl; }
            if (row_hi < N_NODES) { g_as1[row_hi * 4 + head] = sh; g_ad1[row_hi * 4 + head] = dh; }
        }
        if (row_lo < N_NODES) {
            __half* p = g_h1h + (size_t)row_lo * L1_OUT + wn + cb;
#pragma unroll
            for (int ni = 0; ni < 8; ni++)
                *(__half2*)(p + ni * 8) = __floats2half2_rn(acc[mi][ni][0], acc[mi][ni][1]);
        }
        if (row_hi < N_NODES) {
            __half* p = g_h1h + (size_t)row_hi * L1_OUT + wn + cb;
#pragma unroll
            for (int ni = 0; ni < 8; ni++)
                *(__half2*)(p + ni * 8) = __floats2half2_rn(acc[mi][ni][2], acc[mi][ni][3]);
        }
    }
}

// ---------------- layer-1 aggregation: node-range slice, 5 CTAs/SM -----------
__global__ __launch_bounds__(256, 5) void agg1_kernel(const float* __restrict__ b1,
                                                      int nbase, int nend) {
    __shared__ float sx[8][4][32];
    __shared__ int   ss[8][32];
    int wid = threadIdx.x >> 5;
    int gt = blockIdx.x * blockDim.x + threadIdx.x;
    if (gt == 0 && nbase == 0) g_idx_bad = 0;
    int n = nbase + (gt >> 5);
    if (n >= nend) return;
    int lane = threadIdx.x & 31;
    int head = lane >> 3;
    const size_t s0 = (size_t)n * CAP;
    int c = min(g_cnt[n], CAP);
    float4 adv = *(const float4*)(g_ad1 + n * 4);

    float a0=0,a1=0,a2=0,a3=0,a4=0,a5=0,a6=0,a7=0, denom=0.f;

    for (int base = 0; base < c; base += 32) {
        int m = min(32, c - base);
        if (lane < m) {
            int s = __ldg(g_ssrc + s0 + base + lane);
            float4 av = __ldg((const float4*)(g_as1 + s * 4));
            ss[wid][lane]    = s;
            sx[wid][0][lane] = __expf(lrelu(av.x + adv.x));
            sx[wid][1][lane] = __expf(lrelu(av.y + adv.y));
            sx[wid][2][lane] = __expf(lrelu(av.z + adv.z));
            sx[wid][3][lane] = __expf(lrelu(av.w + adv.w));
        }
        __syncwarp();
        int j = 0;
        for (; j + 4 <= m; j += 4) {
            int   sA = ss[wid][j],       sB = ss[wid][j + 1];
            int   sC = ss[wid][j + 2],   sD = ss[wid][j + 3];
            float xA = sx[wid][head][j],     xB = sx[wid][head][j + 1];
            float xC = sx[wid][head][j + 2], xD = sx[wid][head][j + 3];
            uint4 uA = __ldg((const uint4*)(g_h1h + (size_t)sA * L1_OUT + (lane << 3)));
            uint4 uB = __ldg((const uint4*)(g_h1h + (size_t)sB * L1_OUT + (lane << 3)));
            uint4 uC = __ldg((const uint4*)(g_h1h + (size_t)sC * L1_OUT + (lane << 3)));
            uint4 uD = __ldg((const uint4*)(g_h1h + (size_t)sD * L1_OUT + (lane << 3)));
            denom += (xA + xB) + (xC + xD);
            {
                float2 f0 = __half22float2(*(__half2*)&uA.x);
                float2 f1 = __half22float2(*(((__half2*)&uA.x) + 1));
                float2 f2 = __half22float2(*(__half2*)&uA.z);
                float2 f3 = __half22float2(*(((__half2*)&uA.z) + 1));
                a0 = fmaf(xA, f0.x, a0); a1 = fmaf(xA, f0.y, a1);
                a2 = fmaf(xA, f1.x, a2); a3 = fmaf(xA, f1.y, a3);
                a4 = fmaf(xA, f2.x, a4); a5 = fmaf(xA, f2.y, a5);
                a6 = fmaf(xA, f3.x, a6); a7 = fmaf(xA, f3.y, a7);
            }
            {
                float2 f0 = __half22float2(*(__half2*)&uB.x);
                float2 f1 = __half22float2(*(((__half2*)&uB.x) + 1));
                float2 f2 = __half22float2(*(__half2*)&uB.z);
                float2 f3 = __half22float2(*(((__half2*)&uB.z) + 1));
                a0 = fmaf(xB, f0.x, a0); a1 = fmaf(xB, f0.y, a1);
                a2 = fmaf(xB, f1.x, a2); a3 = fmaf(xB, f1.y, a3);
                a4 = fmaf(xB, f2.x, a4); a5 = fmaf(xB, f2.y, a5);
                a6 = fmaf(xB, f3.x, a6); a7 = fmaf(xB, f3.y, a7);
            }
            {
                float2 f0 = __half22float2(*(__half2*)&uC.x);
                float2 f1 = __half22float2(*(((__half2*)&uC.x) + 1));
                float2 f2 = __half22float2(*(__half2*)&uC.z);
                float2 f3 = __half22float2(*(((__half2*)&uC.z) + 1));
                a0 = fmaf(xC, f0.x, a0); a1 = fmaf(xC, f0.y, a1);
                a2 = fmaf(xC, f1.x, a2); a3 = fmaf(xC, f1.y, a3);
                a4 = fmaf(xC, f2.x, a4); a5 = fmaf(xC, f2.y, a5);
                a6 = fmaf(xC, f3.x, a6); a7 = fmaf(xC, f3.y, a7);
            }
            {
                float2 f0 = __half22float2(*(__half2*)&uD.x);
                float2 f1 = __half22float2(*(((__half2*)&uD.x) + 1));
                float2 f2 = __half22float2(*(__half2*)&uD.z);
                float2 f3 = __half22float2(*(((__half2*)&uD.z) + 1));
                a0 = fmaf(xD, f0.x, a0); a1 = fmaf(xD, f0.y, a1);
                a2 = fmaf(xD, f1.x, a2); a3 = fmaf(xD, f1.y, a3);
                a4 = fmaf(xD, f2.x, a4); a5 = fmaf(xD, f2.y, a5);
                a6 = fmaf(xD, f3.x, a6); a7 = fmaf(xD, f3.y, a7);
            }
        }
        for (; j < m; j++) {
            int   s  = ss[wid][j];
            float xh = sx[wid][head][j];
            uint4 u = __ldg((const uint4*)(g_h1h + (size_t)s * L1_OUT + (lane << 3)));
            float2 f0 = __half22float2(*(__half2*)&u.x);
            float2 f1 = __half22float2(*(((__half2*)&u.x) + 1));
            float2 f2 = __half22float2(*(__half2*)&u.z);
            float2 f3 = __half22float2(*(((__half2*)&u.z) + 1));
            denom += xh;
            a0 = fmaf(xh, f0.x, a0); a1 = fmaf(xh, f0.y, a1);
            a2 = fmaf(xh, f1.x, a2); a3 = fmaf(xh, f1.y, a3);
            a4 = fmaf(xh, f2.x, a4); a5 = fmaf(xh, f2.y, a5);
            a6 = fmaf(xh, f3.x, a6); a7 = fmaf(xh, f3.y, a7);
        }
        __syncwarp();
    }

    float inv = 1.0f / (denom + EPS);
    int col = lane * 8;
    float4 bA = *(const float4*)(b1 + col);
    float4 bB = *(const float4*)(b1 + col + 4);
    __half2 o[4];
    o[0] = __floats2half2_rn(fmaxf(0.f, fmaf(a0, inv, bA.x)), fmaxf(0.f, fmaf(a1, inv, bA.y)));
    o[1] = __floats2half2_rn(fmaxf(0.f, fmaf(a2, inv, bA.z)), fmaxf(0.f, fmaf(a3, inv, bA.w)));
    o[2] = __floats2half2_rn(fmaxf(0.f, fmaf(a4, inv, bB.x)), fmaxf(0.f, fmaf(a5, inv, bB.y)));
    o[3] = __floats2half2_rn(fmaxf(0.f, fmaf(a6, inv, bB.z)), fmaxf(0.f, fmaf(a7, inv, bB.w)));
    *(uint4*)(g_out1h + (size_t)n * L1_OUT + col) = *(uint4*)o;
}

// ---------------- GEMM2 via HMMA (tile-offset param) --------------------------
#define G2APAD 40
#define G2BPAD 56
__global__ __launch_bounds__(256) void gemm2_kernel(
    const float* __restrict__ W2,
    const float* __restrict__ a_src, const float* __restrict__ a_dst,
    int tile0)
{
    __shared__ __half As[128 * G2APAD];
    __shared__ __half Bs[L1_OUT * G2BPAD];
    const int tid = threadIdx.x;
    const int wid = tid >> 5, lane = tid & 31;
    const int bm = (tile0 + blockIdx.x) * 128;
    const int wm = wid * 16;

    for (int i = tid; i < L1_OUT * CLASSES; i += 256) {
        int r = i / CLASSES, cc = i - r * CLASSES;
        Bs[r * G2BPAD + cc] = __float2half_rn(__ldg(W2 + i));
    }

    const int ar = tid >> 1;
    const int ac = (tid & 1) * 16;
    const __half* Ap = g_out1h + (size_t)(bm + ar) * L1_OUT + ac;
    const bool aval = (bm + ar) < N_NODES;
    const uint4 zz = make_uint4(0, 0, 0, 0);

    uint4 ra0 = aval ? __ldg((const uint4*)Ap)       : zz;
    uint4 ra1 = aval ? __ldg((const uint4*)(Ap + 8)) : zz;

    float acc[5][4];
#pragma unroll
    for (int nt = 0; nt < 5; nt++)
#pragma unroll
        for (int q = 0; q < 4; q++) acc[nt][q] = 0.f;

    const uint32_t a_addr = smem_u32(As + (wm + (lane & 15)) * G2APAD + (lane >> 4) * 8);
    const uint32_t b_row  = smem_u32(Bs + (lane & 15) * G2BPAD);

    for (int kk = 0; kk < L1_OUT / 32; kk++) {
        __syncthreads();
        *(uint4*)(As + ar * G2APAD + ac)     = ra0;
        *(uint4*)(As + ar * G2APAD + ac + 8) = ra1;
        __syncthreads();
        if (kk < L1_OUT / 32 - 1) {
            const __half* p = Ap + (kk + 1) * 32;
            ra0 = aval ? __ldg((const uint4*)p)       : zz;
            ra1 = aval ? __ldg((const uint4*)(p + 8)) : zz;
        }
#pragma unroll
        for (int k16 = 0; k16 < 2; k16++) {
            uint32_t af[4];
            ldmatrix_x4(af, a_addr + k16 * 32);
            int k0 = kk * 32 + k16 * 16;
#pragma unroll
            for (int nt = 0; nt < 5; nt++) {
                uint32_t bf[2];
                ldmatrix_x2_trans(bf, b_row + (uint32_t)k0 * (G2BPAD * 2) + nt * 16);
                mma16816(acc[nt], af, bf);
            }
        }
    }

    const int cb = (lane & 3) * 2;
    float ps_lo = 0.f, ps_hi = 0.f, pd_lo = 0.f, pd_hi = 0.f;
#pragma unroll
    for (int nt = 0; nt < 5; nt++) {
        int col = nt * 8 + cb;
        float s0 = __ldg(a_src + col), s1 = __ldg(a_src + col + 1);
        float d0 = __ldg(a_dst + col), d1 = __ldg(a_dst + col + 1);
        ps_lo = fmaf(acc[nt][0], s0, fmaf(acc[nt][1], s1, ps_lo));
        ps_hi = fmaf(acc[nt][2], s0, fmaf(acc[nt][3], s1, ps_hi));
        pd_lo = fmaf(acc[nt][0], d0, fmaf(acc[nt][1], d1, pd_lo));
        pd_hi = fmaf(acc[nt][2], d0, fmaf(acc[nt][3], d1, pd_hi));
    }
#pragma unroll
    for (int s = 1; s < 4; s <<= 1) {
        ps_lo += __shfl_xor_sync(0xffffffffu, ps_lo, s);
        ps_hi += __shfl_xor_sync(0xffffffffu, ps_hi, s);
        pd_lo += __shfl_xor_sync(0xffffffffu, pd_lo, s);
        pd_hi += __shfl_xor_sync(0xffffffffu, pd_hi, s);
    }
    int row_lo = bm + wm + (lane >> 2);
    int row_hi = row_lo + 8;
    if ((lane & 3) == 0) {
        if (row_lo < N_NODES) { g_as2[row_lo] = ps_lo; g_ad2[row_lo] = pd_lo; }
        if (row_hi < N_NODES) { g_as2[row_hi] = ps_hi; g_ad2[row_hi] = pd_hi; }
    }
    if (row_lo < N_NODES) {
        __half* p = g_h2h + (size_t)row_lo * CLASSES + cb;
#pragma unroll
        for (int nt = 0; nt < 5; nt++)
            *(__half2*)(p + nt * 8) = __floats2half2_rn(acc[nt][0], acc[nt][1]);
    }
    if (row_hi < N_NODES) {
        __half* p = g_h2h + (size_t)row_hi * CLASSES + cb;
#pragma unroll
        for (int nt = 0; nt < 5; nt++)
            *(__half2*)(p + nt * 8) = __floats2half2_rn(acc[nt][2], acc[nt][3]);
    }
}

// ---------------- layer-2 aggregation + fused log_softmax --------------------
__global__ __launch_bounds__(256) void agg2_kernel(const float* __restrict__ b2,
                                                   float* __restrict__ out) {
    __shared__ float sx[8][32];
    __shared__ int   ss[8][32];
    int wid = threadIdx.x >> 5;
    int n = (blockIdx.x * blockDim.x + threadIdx.x) >> 5;
    if (n >= N_NODES) return;
    int lane = threadIdx.x & 31;
    bool act = lane < 20;
    const size_t s0 = (size_t)n * CAP;
    int c = min(g_cnt[n], CAP);
    float adn = __ldg(g_ad2 + n);

    float acc0 = 0.f, acc1 = 0.f, denom = 0.f;
    for (int base = 0; base < c; base += 32) {
        int m = min(32, c - base);
        if (lane < m) {
            int s = __ldg(g_ssrc + s0 + base + lane);
            float e = __ldg(g_as2 + s);
            ss[wid][lane] = s;
            sx[wid][lane] = __expf(lrelu(e + adn));
        }
        __syncwarp();
        int j = 0;
        for (; j + 2 <= m; j += 2) {
            int   sA = ss[wid][j],  sB = ss[wid][j + 1];
            float xA = sx[wid][j],  xB = sx[wid][j + 1];
            denom += xA + xB;
            if (act) {
                __half2 hA = __ldg((const __half2*)(g_h2h + (size_t)sA * CLASSES + 2 * lane));
                __half2 hB = __ldg((const __half2*)(g_h2h + (size_t)sB * CLASSES + 2 * lane));
                float2 fA = __half22float2(hA);
                float2 fB = __half22float2(hB);
                acc0 = fmaf(xA, fA.x, fmaf(xB, fB.x, acc0));
                acc1 = fmaf(xA, fA.y, fmaf(xB, fB.y, acc1));
            }
        }
        if (j < m) {
            int   s = ss[wid][j];
            float x = sx[wid][j];
            denom += x;
            if (act) {
                __half2 h = __ldg((const __half2*)(g_h2h + (size_t)s * CLASSES + 2 * lane));
                float2 f = __half22float2(h);
                acc0 = fmaf(x, f.x, acc0);
                acc1 = fmaf(x, f.y, acc1);
            }
        }
        __syncwarp();
    }
    float inv = 1.0f / (denom + EPS);
    float o0 = act ? fmaf(acc0, inv, __ldg(b2 + 2 * lane))     : -1e30f;
    float o1 = act ? fmaf(acc1, inv, __ldg(b2 + 2 * lane + 1)) : -1e30f;

    float mx = warpMax(fmaxf(o0, o1));
    float se = act ? (__expf(o0 - mx) + __expf(o1 - mx)) : 0.f;
    se = warpSum(se);
    float ls = __logf(se);
    if (act) {
        out[(size_t)n * CLASSES + 2 * lane]     = o0 - mx - ls;
        out[(size_t)n * CLASSES + 2 * lane + 1] = o1 - mx - ls;
    }
}

// ---------------- launch: fork-join + agg1/gemm2 pipelining ------------------
extern "C" void kernel_launch(void* const* d_in, const int* in_sizes, int n_in,
                              void* d_out, int out_size) {
    const float* x    = (const float*)d_in[0];
    const void*  ei   = d_in[1];
    const float* W1   = (const float*)d_in[2];
    const float* asr1 = (const float*)d_in[3];
    const float* adt1 = (const float*)d_in[4];
    const float* b1   = (const float*)d_in[5];
    const float* W2   = (const float*)d_in[6];
    const float* asr2 = (const float*)d_in[7];
    const float* adt2 = (const float*)d_in[8];
    const float* b2   = (const float*)d_in[9];
    float* out = (float*)d_out;

    static cudaStream_t s_side = nullptr;
    static cudaEvent_t  s_fork = nullptr, s_join = nullptr, s_e1 = nullptr, s_e2 = nullptr;
    if (s_side == nullptr) {
        cudaStreamCreateWithFlags(&s_side, cudaStreamNonBlocking);
        cudaEventCreateWithFlags(&s_fork, cudaEventDisableTiming);
        cudaEventCreateWithFlags(&s_join, cudaEventDisableTiming);
        cudaEventCreateWithFlags(&s_e1, cudaEventDisableTiming);
        cudaEventCreateWithFlags(&s_e2, cudaEventDisableTiming);
    }

    // fork: edge pipeline beside GEMM1
    cudaEventRecord(s_fork, 0);
    cudaStreamWaitEvent(s_side, s_fork, 0);
    prep_kernel<<<PREP_BLOCKS, 256, 0, s_side>>>((const long long*)ei);
    scatter_kernel<<<SCAT_BLOCKS, 256, 0, s_side>>>(ei);
    cudaEventRecord(s_join, s_side);

    kGemm1<<<GEMM1_TILES, 256>>>(x, W1, asr1, adt1);
    cudaStreamWaitEvent(0, s_join, 0);

    // agg1 first half -> (gemm2 first half on side) || agg1 second half
    agg1_kernel<<<AGG1_BLK_A, 256>>>(b1, 0, SPLIT_NODE);
    cudaEventRecord(s_e1, 0);
    agg1_kernel<<<AGG1_BLK_B, 256>>>(b1, SPLIT_NODE, N_NODES);

    cudaStreamWaitEvent(s_side, s_e1, 0);
    gemm2_kernel<<<G2_TILES_A, 256, 0, s_side>>>(W2, asr2, adt2, 0);
    cudaEventRecord(s_e2, s_side);

    gemm2_kernel<<<G2_TILES_B, 256>>>(W2, asr2, adt2, G2_TILES_A);
    cudaStreamWaitEvent(0, s_e2, 0);

    agg2_kernel<<<(N_NODES + 7) / 8, 256>>>(b2, out);
}

// round 14
// speedup vs baseline: 1.0706x; 1.0706x over previous
#include <cuda_runtime.h>
#include <cuda_fp16.h>
#include <cstdint>

#define N_NODES 50000
#define N_EDGES 800000
#define F_IN    128
#define HID     64
#define HEADS   4
#define L1_OUT  (HEADS*HID)   // 256
#define CLASSES 40
#define NEG_SLOPE 0.2f
#define EPS 1e-16f
#define CAP   96               // bucket capacity per dst (Poisson(16); P(>=96)~e-60)

#define GEMM1_TILES 391            // ceil(50000/128)
#define SCAT_BLOCKS 1563           // ceil(800000 / (256*2))
#define PREP_BLOCKS 782            // 200000 detect threads / 256

// ---------------- scratch --------------------------------------------------
__device__ __align__(16) __half g_h1h [(size_t)N_NODES * L1_OUT];
__device__ __align__(16) __half g_out1h[(size_t)N_NODES * L1_OUT];
__device__ __align__(16) __half g_h2h [(size_t)N_NODES * CLASSES];
__device__ __align__(16) float g_as1[N_NODES * HEADS];
__device__ __align__(16) float g_ad1[N_NODES * HEADS];
__device__ float g_as2[N_NODES];
__device__ float g_ad2[N_NODES];
__device__ int   g_cnt[N_NODES];
__device__ int   g_ssrc[(size_t)N_NODES * CAP];
__device__ int   g_idx_bad;        // 0 between launches; set by prep, reset by agg1

// ---------------- helpers ---------------------------------------------------
__device__ __forceinline__ float warpMax(float v) {
#pragma unroll
    for (int s = 16; s > 0; s >>= 1)
        v = fmaxf(v, __shfl_xor_sync(0xffffffffu, v, s));
    return v;
}
__device__ __forceinline__ float warpSum(float v) {
#pragma unroll
    for (int s = 16; s > 0; s >>= 1)
        v += __shfl_xor_sync(0xffffffffu, v, s);
    return v;
}
__device__ __forceinline__ float lrelu(float x) {
    return (x > 0.f) ? x : NEG_SLOPE * x;
}
__device__ __forceinline__ uint32_t smem_u32(const void* p) {
    return (uint32_t)__cvta_generic_to_shared(p);
}
__device__ __forceinline__ void ldmatrix_x4(uint32_t* r, uint32_t addr) {
    asm volatile("ldmatrix.sync.aligned.m8n8.x4.shared.b16 {%0,%1,%2,%3}, [%4];"
                 : "=r"(r[0]), "=r"(r[1]), "=r"(r[2]), "=r"(r[3]) : "r"(addr));
}
__device__ __forceinline__ void ldmatrix_x4_trans(uint32_t* r, uint32_t addr) {
    asm volatile("ldmatrix.sync.aligned.m8n8.x4.trans.shared.b16 {%0,%1,%2,%3}, [%4];"
                 : "=r"(r[0]), "=r"(r[1]), "=r"(r[2]), "=r"(r[3]) : "r"(addr));
}
__device__ __forceinline__ void ldmatrix_x2_trans(uint32_t* r, uint32_t addr) {
    asm volatile("ldmatrix.sync.aligned.m8n8.x2.trans.shared.b16 {%0,%1}, [%2];"
                 : "=r"(r[0]), "=r"(r[1]) : "r"(addr));
}
__device__ __forceinline__ void mma16816(float* c, const uint32_t* a, const uint32_t* b) {
    asm volatile(
        "mma.sync.aligned.m16n8k16.row.col.f32.f16.f16.f32 "
        "{%0,%1,%2,%3}, {%4,%5,%6,%7}, {%8,%9}, {%0,%1,%2,%3};"
        : "+f"(c[0]), "+f"(c[1]), "+f"(c[2]), "+f"(c[3])
        : "r"(a[0]), "r"(a[1]), "r"(a[2]), "r"(a[3]), "r"(b[0]), "r"(b[1]));
}

// ---------------- prep: zero counts + sampled dtype detection ----------------
__global__ void prep_kernel(const long long* __restrict__ ei) {
    int i = blockIdx.x * blockDim.x + threadIdx.x;
    if (i < N_NODES) g_cnt[i] = 0;
    int e = i * 4;
    if (e < N_EDGES) {
        long long v = __ldg(ei + e);
        if (v < 0 || v >= N_NODES) g_idx_bad = 1;
    }
}

// ---------------- bucket scatter (2 edges/thread) -----------------------------
__global__ void scatter_kernel(const void* __restrict__ eiv) {
    int e0 = (blockIdx.x * 256 + threadIdx.x) * 2;
    if (e0 >= N_EDGES) return;
    int s0, s1, d0, d1;
    if (!g_idx_bad) {
        longlong2 a = __ldg((const longlong2*)((const long long*)eiv + e0));
        longlong2 d = __ldg((const longlong2*)((const long long*)eiv + N_EDGES + e0));
        s0 = (int)a.x; s1 = (int)a.y; d0 = (int)d.x; d1 = (int)d.y;
    } else {
        int2 a = __ldg((const int2*)((const int*)eiv + e0));
        int2 d = __ldg((const int2*)((const int*)eiv + N_EDGES + e0));
        s0 = a.x; s1 = a.y; d0 = d.x; d1 = d.y;
    }
    int p0 = atomicAdd(&g_cnt[d0], 1);
    if (p0 < CAP) g_ssrc[(size_t)d0 * CAP + p0] = s0;
    int p1 = atomicAdd(&g_cnt[d1], 1);
    if (p1 < CAP) g_ssrc[(size_t)d1 * CAP + p1] = s1;
}

// ---------------- GEMM1 via HMMA (unchanged) ----------------------------------
#define APAD 40
#define BPAD 264
__global__ __launch_bounds__(256) void kGemm1(
    const float* __restrict__ A, const float* __restrict__ B,
    const float* __restrict__ a_src, const float* __restrict__ a_dst)
{
    __shared__ __half smem[128 * APAD + 32 * BPAD];
    __half* As = smem;                 // [128][APAD]
    __half* Bs = smem + 128 * APAD;    // [32][BPAD]
    const int tid = threadIdx.x;
    const int wid = tid >> 5, lane = tid & 31;
    const int bm = blockIdx.x * 128;
    const int wm = (wid >> 2) * 64;
    const int wn = (wid & 3) * 64;
    const int head = wid & 3;

    const int ar = tid >> 1;
    const int ac = (tid & 1) * 16;
    const int br = tid >> 3;
    const int bc = (tid & 7) * 32;

    const float* Ap = A + (size_t)(bm + ar) * F_IN + ac;
    const bool aval = (bm + ar) < N_NODES;
    const float* Bp = B + (size_t)br * L1_OUT + bc;
    const float4 z = make_float4(0.f, 0.f, 0.f, 0.f);

    float acc[4][8][4];
#pragma unroll
    for (int i = 0; i < 4; i++)
#pragma unroll
        for (int j = 0; j < 8; j++)
#pragma unroll
            for (int q = 0; q < 4; q++) acc[i][j][q] = 0.f;

    float4 ra[4], rb[8];
#pragma unroll
    for (int q = 0; q < 4; q++) ra[q] = aval ? __ldg((const float4*)(Ap + q * 4)) : z;
#pragma unroll
    for (int q = 0; q < 8; q++) rb[q] = __ldg((const float4*)(Bp + q * 4));

    uint32_t a_addr[4], b_addr[4];
#pragma unroll
    for (int mi = 0; mi < 4; mi++)
        a_addr[mi] = smem_u32(As + (wm + mi * 16 + (lane & 15)) * APAD + (lane >> 4) * 8);
#pragma unroll
    for (int nj = 0; nj < 4; nj++)
        b_addr[nj] = smem_u32(Bs + (lane & 15) * BPAD + wn + nj * 16 + (lane >> 4) * 8);

    for (int kk = 0; kk < F_IN / 32; kk++) {
        if (kk > 0) __syncthreads();
        {
            __half2* Arow = (__half2*)(As + ar * APAD + ac);
#pragma unroll
            for (int q = 0; q < 4; q++) {
                Arow[q * 2]     = __floats2half2_rn(ra[q].x, ra[q].y);
                Arow[q * 2 + 1] = __floats2half2_rn(ra[q].z, ra[q].w);
            }
            __half2* Brow = (__half2*)(Bs + br * BPAD + bc);
#pragma unroll
            for (int q = 0; q < 8; q++) {
                Brow[q * 2]     = __floats2half2_rn(rb[q].x, rb[q].y);
                Brow[q * 2 + 1] = __floats2half2_rn(rb[q].z, rb[q].w);
            }
        }
        __syncthreads();
        if (kk < F_IN / 32 - 1) {
            int k0 = (kk + 1) * 32;
#pragma unroll
            for (int q = 0; q < 4; q++)
                ra[q] = aval ? __ldg((const float4*)(Ap + k0 + q * 4)) : z;
#pragma unroll
            for (int q = 0; q < 8; q++)
                rb[q] = __ldg((const float4*)(Bp + (size_t)k0 * L1_OUT + q * 4));
        }
#pragma unroll
        for (int k16 = 0; k16 < 2; k16++) {
            uint32_t af[4][4], bf[8][2];
#pragma unroll
            for (int mi = 0; mi < 4; mi++)
                ldmatrix_x4(af[mi], a_addr[mi] + k16 * 32);
#pragma unroll
            for (int nj = 0; nj < 4; nj++) {
                uint32_t t[4];
                ldmatrix_x4_trans(t, b_addr[nj] + k16 * 16 * BPAD * 2);
                bf[nj * 2][0] = t[0]; bf[nj * 2][1] = t[1];
                bf[nj * 2 + 1][0] = t[2]; bf[nj * 2 + 1][1] = t[3];
            }
#pragma unroll
            for (int mi = 0; mi < 4; mi++)
#pragma unroll
                for (int ni = 0; ni < 8; ni++)
                    mma16816(acc[mi][ni], af[mi], bf[ni]);
        }
    }

    float as0[8], as1[8], ad0[8], ad1[8];
    int cb = (lane & 3) * 2;
#pragma unroll
    for (int ni = 0; ni < 8; ni++) {
        int col = wn + ni * 8 + cb;
        as0[ni] = __ldg(a_src + col); as1[ni] = __ldg(a_src + col + 1);
        ad0[ni] = __ldg(a_dst + col); ad1[ni] = __ldg(a_dst + col + 1);
    }
#pragma unroll
    for (int mi = 0; mi < 4; mi++) {
        float sl = 0.f, sh = 0.f, dl = 0.f, dh = 0.f;
#pragma unroll
        for (int ni = 0; ni < 8; ni++) {
            sl = fmaf(acc[mi][ni][0], as0[ni], fmaf(acc[mi][ni][1], as1[ni], sl));
            sh = fmaf(acc[mi][ni][2], as0[ni], fmaf(acc[mi][ni][3], as1[ni], sh));
            dl = fmaf(acc[mi][ni][0], ad0[ni], fmaf(acc[mi][ni][1], ad1[ni], dl));
            dh = fmaf(acc[mi][ni][2], ad0[ni], fmaf(acc[mi][ni][3], ad1[ni], dh));
        }
#pragma unroll
        for (int s = 1; s < 4; s <<= 1) {
            sl += __shfl_xor_sync(0xffffffffu, sl, s);
            sh += __shfl_xor_sync(0xffffffffu, sh, s);
            dl += __shfl_xor_sync(0xffffffffu, dl, s);
            dh += __shfl_xor_sync(0xffffffffu, dh, s);
        }
        int row_lo = bm + wm + mi * 16 + (lane >> 2);
        int row_hi = row_lo + 8;
        if ((lane & 3) == 0) {
            if (row_lo < N_NODES) { g_as1[row_lo * 4 + head] = sl; g_ad1[row_lo * 4 + head] = dl; }
            if (row_hi < N_NODES) { g_as1[row_hi * 4 + head] = sh; g_ad1[row_hi * 4 + head] = dh; }
        }
        if (row_lo < N_NODES) {
            __half* p = g_h1h + (size_t)row_lo * L1_OUT + wn + cb;
#pragma unroll
            for (int ni = 0; ni < 8; ni++)
                *(__half2*)(p + ni * 8) = __floats2half2_rn(acc[mi][ni][0], acc[mi][ni][1]);
        }
        if (row_hi < N_NODES) {
            __half* p = g_h1h + (size_t)row_hi * L1_OUT + wn + cb;
#pragma unroll
            for (int ni = 0; ni < 8; ni++)
                *(__half2*)(p + ni * 8) = __floats2half2_rn(acc[mi][ni][2], acc[mi][ni][3]);
        }
    }
}

// ---------------- layer-1 aggregation: 128-thread blocks, R12 body -----------
__global__ __launch_bounds__(128) void agg1_kernel(const float* __restrict__ b1) {
    __shared__ float sx[4][4][32];
    __shared__ int   ss[4][32];
    int wid = threadIdx.x >> 5;
    int gt = blockIdx.x * blockDim.x + threadIdx.x;
    if (gt == 0) g_idx_bad = 0;
    int n = gt >> 5;
    if (n >= N_NODES) return;
    int lane = threadIdx.x & 31;
    int head = lane >> 3;
    const size_t s0 = (size_t)n * CAP;
    int c = min(g_cnt[n], CAP);
    float4 adv = *(const float4*)(g_ad1 + n * 4);

    float a0=0,a1=0,a2=0,a3=0,a4=0,a5=0,a6=0,a7=0, denom=0.f;

    for (int base = 0; base < c; base += 32) {
        int m = min(32, c - base);
        if (lane < m) {
            int s = __ldg(g_ssrc + s0 + base + lane);
            float4 av = __ldg((const float4*)(g_as1 + s * 4));
            ss[wid][lane]    = s;
            sx[wid][0][lane] = __expf(lrelu(av.x + adv.x));
            sx[wid][1][lane] = __expf(lrelu(av.y + adv.y));
            sx[wid][2][lane] = __expf(lrelu(av.z + adv.z));
            sx[wid][3][lane] = __expf(lrelu(av.w + adv.w));
        }
        __syncwarp();
        int j = 0;
        for (; j + 4 <= m; j += 4) {
            int   sA = ss[wid][j],       sB = ss[wid][j + 1];
            int   sC = ss[wid][j + 2],   sD = ss[wid][j + 3];
            float xA = sx[wid][head][j],     xB = sx[wid][head][j + 1];
            float xC = sx[wid][head][j + 2], xD = sx[wid][head][j + 3];
            uint4 uA = __ldg((const uint4*)(g_h1h + (size_t)sA * L1_OUT + (lane << 3)));
            uint4 uB = __ldg((const uint4*)(g_h1h + (size_t)sB * L1_OUT + (lane << 3)));
            uint4 uC = __ldg((const uint4*)(g_h1h + (size_t)sC * L1_OUT + (lane << 3)));
            uint4 uD = __ldg((const uint4*)(g_h1h + (size_t)sD * L1_OUT + (lane << 3)));
            denom += (xA + xB) + (xC + xD);
            {
                float2 f0 = __half22float2(*(__half2*)&uA.x);
                float2 f1 = __half22float2(*(((__half2*)&uA.x) + 1));
                float2 f2 = __half22float2(*(__half2*)&uA.z);
                float2 f3 = __half22float2(*(((__half2*)&uA.z) + 1));
                a0 = fmaf(xA, f0.x, a0); a1 = fmaf(xA, f0.y, a1);
                a2 = fmaf(xA, f1.x, a2); a3 = fmaf(xA, f1.y, a3);
                a4 = fmaf(xA, f2.x, a4); a5 = fmaf(xA, f2.y, a5);
                a6 = fmaf(xA, f3.x, a6); a7 = fmaf(xA, f3.y, a7);
            }
            {
                float2 f0 = __half22float2(*(__half2*)&uB.x);
                float2 f1 = __half22float2(*(((__half2*)&uB.x) + 1));
                float2 f2 = __half22float2(*(__half2*)&uB.z);
                float2 f3 = __half22float2(*(((__half2*)&uB.z) + 1));
                a0 = fmaf(xB, f0.x, a0); a1 = fmaf(xB, f0.y, a1);
                a2 = fmaf(xB, f1.x, a2); a3 = fmaf(xB, f1.y, a3);
                a4 = fmaf(xB, f2.x, a4); a5 = fmaf(xB, f2.y, a5);
                a6 = fmaf(xB, f3.x, a6); a7 = fmaf(xB, f3.y, a7);
            }
            {
                float2 f0 = __half22float2(*(__half2*)&uC.x);
                float2 f1 = __half22float2(*(((__half2*)&uC.x) + 1));
                float2 f2 = __half22float2(*(__half2*)&uC.z);
                float2 f3 = __half22float2(*(((__half2*)&uC.z) + 1));
                a0 = fmaf(xC, f0.x, a0); a1 = fmaf(xC, f0.y, a1);
                a2 = fmaf(xC, f1.x, a2); a3 = fmaf(xC, f1.y, a3);
                a4 = fmaf(xC, f2.x, a4); a5 = fmaf(xC, f2.y, a5);
                a6 = fmaf(xC, f3.x, a6); a7 = fmaf(xC, f3.y, a7);
            }
            {
                float2 f0 = __half22float2(*(__half2*)&uD.x);
                float2 f1 = __half22float2(*(((__half2*)&uD.x) + 1));
                float2 f2 = __half22float2(*(__half2*)&uD.z);
                float2 f3 = __half22float2(*(((__half2*)&uD.z) + 1));
                a0 = fmaf(xD, f0.x, a0); a1 = fmaf(xD, f0.y, a1);
                a2 = fmaf(xD, f1.x, a2); a3 = fmaf(xD, f1.y, a3);
                a4 = fmaf(xD, f2.x, a4); a5 = fmaf(xD, f2.y, a5);
                a6 = fmaf(xD, f3.x, a6); a7 = fmaf(xD, f3.y, a7);
            }
        }
        for (; j < m; j++) {
            int   s  = ss[wid][j];
            float xh = sx[wid][head][j];
            uint4 u = __ldg((const uint4*)(g_h1h + (size_t)s * L1_OUT + (lane << 3)));
            float2 f0 = __half22float2(*(__half2*)&u.x);
            float2 f1 = __half22float2(*(((__half2*)&u.x) + 1));
            float2 f2 = __half22float2(*(__half2*)&u.z);
            float2 f3 = __half22float2(*(((__half2*)&u.z) + 1));
            denom += xh;
            a0 = fmaf(xh, f0.x, a0); a1 = fmaf(xh, f0.y, a1);
            a2 = fmaf(xh, f1.x, a2); a3 = fmaf(xh, f1.y, a3);
            a4 = fmaf(xh, f2.x, a4); a5 = fmaf(xh, f2.y, a5);
            a6 = fmaf(xh, f3.x, a6); a7 = fmaf(xh, f3.y, a7);
        }
        __syncwarp();
    }

    float inv = 1.0f / (denom + EPS);
    int col = lane * 8;
    float4 bA = *(const float4*)(b1 + col);
    float4 bB = *(const float4*)(b1 + col + 4);
    __half2 o[4];
    o[0] = __floats2half2_rn(fmaxf(0.f, fmaf(a0, inv, bA.x)), fmaxf(0.f, fmaf(a1, inv, bA.y)));
    o[1] = __floats2half2_rn(fmaxf(0.f, fmaf(a2, inv, bA.z)), fmaxf(0.f, fmaf(a3, inv, bA.w)));
    o[2] = __floats2half2_rn(fmaxf(0.f, fmaf(a4, inv, bB.x)), fmaxf(0.f, fmaf(a5, inv, bB.y)));
    o[3] = __floats2half2_rn(fmaxf(0.f, fmaf(a6, inv, bB.z)), fmaxf(0.f, fmaf(a7, inv, bB.w)));
    *(uint4*)(g_out1h + (size_t)n * L1_OUT + col) = *(uint4*)o;
}

// ---------------- GEMM2 via HMMA (unchanged) ----------------------------------
#define G2APAD 40
#define G2BPAD 56
__global__ __launch_bounds__(256) void gemm2_kernel(
    const float* __restrict__ W2,
    const float* __restrict__ a_src, const float* __restrict__ a_dst)
{
    __shared__ __half As[128 * G2APAD];
    __shared__ __half Bs[L1_OUT * G2BPAD];
    const int tid = threadIdx.x;
    const int wid = tid >> 5, lane = tid & 31;
    const int bm = blockIdx.x * 128;
    const int wm = wid * 16;

    for (int i = tid; i < L1_OUT * CLASSES; i += 256) {
        int r = i / CLASSES, cc = i - r * CLASSES;
        Bs[r * G2BPAD + cc] = __float2half_rn(__ldg(W2 + i));
    }

    const int ar = tid >> 1;
    const int ac = (tid & 1) * 16;
    const __half* Ap = g_out1h + (size_t)(bm + ar) * L1_OUT + ac;
    const bool aval = (bm + ar) < N_NODES;
    const uint4 zz = make_uint4(0, 0, 0, 0);

    uint4 ra0 = aval ? __ldg((const uint4*)Ap)       : zz;
    uint4 ra1 = aval ? __ldg((const uint4*)(Ap + 8)) : zz;

    float acc[5][4];
#pragma unroll
    for (int nt = 0; nt < 5; nt++)
#pragma unroll
        for (int q = 0; q < 4; q++) acc[nt][q] = 0.f;

    const uint32_t a_addr = smem_u32(As + (wm + (lane & 15)) * G2APAD + (lane >> 4) * 8);
    const uint32_t b_row  = smem_u32(Bs + (lane & 15) * G2BPAD);

    for (int kk = 0; kk < L1_OUT / 32; kk++) {
        __syncthreads();
        *(uint4*)(As + ar * G2APAD + ac)     = ra0;
        *(uint4*)(As + ar * G2APAD + ac + 8) = ra1;
        __syncthreads();
        if (kk < L1_OUT / 32 - 1) {
            const __half* p = Ap + (kk + 1) * 32;
            ra0 = aval ? __ldg((const uint4*)p)       : zz;
            ra1 = aval ? __ldg((const uint4*)(p + 8)) : zz;
        }
#pragma unroll
        for (int k16 = 0; k16 < 2; k16++) {
            uint32_t af[4];
            ldmatrix_x4(af, a_addr + k16 * 32);
            int k0 = kk * 32 + k16 * 16;
#pragma unroll
            for (int nt = 0; nt < 5; nt++) {
                uint32_t bf[2];
                ldmatrix_x2_trans(bf, b_row + (uint32_t)k0 * (G2BPAD * 2) + nt * 16);
                mma16816(acc[nt], af, bf);
            }
        }
    }

    const int cb = (lane & 3) * 2;
    float ps_lo = 0.f, ps_hi = 0.f, pd_lo = 0.f, pd_hi = 0.f;
#pragma unroll
    for (int nt = 0; nt < 5; nt++) {
        int col = nt * 8 + cb;
        float s0 = __ldg(a_src + col), s1 = __ldg(a_src + col + 1);
        float d0 = __ldg(a_dst + col), d1 = __ldg(a_dst + col + 1);
        ps_lo = fmaf(acc[nt][0], s0, fmaf(acc[nt][1], s1, ps_lo));
        ps_hi = fmaf(acc[nt][2], s0, fmaf(acc[nt][3], s1, ps_hi));
        pd_lo = fmaf(acc[nt][0], d0, fmaf(acc[nt][1], d1, pd_lo));
        pd_hi = fmaf(acc[nt][2], d0, fmaf(acc[nt][3], d1, pd_hi));
    }
#pragma unroll
    for (int s = 1; s < 4; s <<= 1) {
        ps_lo += __shfl_xor_sync(0xffffffffu, ps_lo, s);
        ps_hi += __shfl_xor_sync(0xffffffffu, ps_hi, s);
        pd_lo += __shfl_xor_sync(0xffffffffu, pd_lo, s);
        pd_hi += __shfl_xor_sync(0xffffffffu, pd_hi, s);
    }
    int row_lo = bm + wm + (lane >> 2);
    int row_hi = row_lo + 8;
    if ((lane & 3) == 0) {
        if (row_lo < N_NODES) { g_as2[row_lo] = ps_lo; g_ad2[row_lo] = pd_lo; }
        if (row_hi < N_NODES) { g_as2[row_hi] = ps_hi; g_ad2[row_hi] = pd_hi; }
    }
    if (row_lo < N_NODES) {
        __half* p = g_h2h + (size_t)row_lo * CLASSES + cb;
#pragma unroll
        for (int nt = 0; nt < 5; nt++)
            *(__half2*)(p + nt * 8) = __floats2half2_rn(acc[nt][0], acc[nt][1]);
    }
    if (row_hi < N_NODES) {
        __half* p = g_h2h + (size_t)row_hi * CLASSES + cb;
#pragma unroll
        for (int nt = 0; nt < 5; nt++)
            *(__half2*)(p + nt * 8) = __floats2half2_rn(acc[nt][2], acc[nt][3]);
    }
}

// ---------------- layer-2 aggregation + fused log_softmax --------------------
__global__ __launch_bounds__(256) void agg2_kernel(const float* __restrict__ b2,
                                                   float* __restrict__ out) {
    __shared__ float sx[8][32];
    __shared__ int   ss[8][32];
    int wid = threadIdx.x >> 5;
    int n = (blockIdx.x * blockDim.x + threadIdx.x) >> 5;
    if (n >= N_NODES) return;
    int lane = threadIdx.x & 31;
    bool act = lane < 20;
    const size_t s0 = (size_t)n * CAP;
    int c = min(g_cnt[n], CAP);
    float adn = __ldg(g_ad2 + n);

    float acc0 = 0.f, acc1 = 0.f, denom = 0.f;
    for (int base = 0; base < c; base += 32) {
        int m = min(32, c - base);
        if (lane < m) {
            int s = __ldg(g_ssrc + s0 + base + lane);
            float e = __ldg(g_as2 + s);
            ss[wid][lane] = s;
            sx[wid][lane] = __expf(lrelu(e + adn));
        }
        __syncwarp();
        int j = 0;
        for (; j + 2 <= m; j += 2) {
            int   sA = ss[wid][j],  sB = ss[wid][j + 1];
            float xA = sx[wid][j],  xB = sx[wid][j + 1];
            denom += xA + xB;
            if (act) {
                __half2 hA = __ldg((const __half2*)(g_h2h + (size_t)sA * CLASSES + 2 * lane));
                __half2 hB = __ldg((const __half2*)(g_h2h + (size_t)sB * CLASSES + 2 * lane));
                float2 fA = __half22float2(hA);
                float2 fB = __half22float2(hB);
                acc0 = fmaf(xA, fA.x, fmaf(xB, fB.x, acc0));
                acc1 = fmaf(xA, fA.y, fmaf(xB, fB.y, acc1));
            }
        }
        if (j < m) {
            int   s = ss[wid][j];
            float x = sx[wid][j];
            denom += x;
            if (act) {
                __half2 h = __ldg((const __half2*)(g_h2h + (size_t)s * CLASSES + 2 * lane));
                float2 f = __half22float2(h);
                acc0 = fmaf(x, f.x, acc0);
                acc1 = fmaf(x, f.y, acc1);
            }
        }
        __syncwarp();
    }
    float inv = 1.0f / (denom + EPS);
    float o0 = act ? fmaf(acc0, inv, __ldg(b2 + 2 * lane))     : -1e30f;
    float o1 = act ? fmaf(acc1, inv, __ldg(b2 + 2 * lane + 1)) : -1e30f;

    float mx = warpMax(fmaxf(o0, o1));
    float se = act ? (__expf(o0 - mx) + __expf(o1 - mx)) : 0.f;
    se = warpSum(se);
    float ls = __logf(se);
    if (act) {
        out[(size_t)n * CLASSES + 2 * lane]     = o0 - mx - ls;
        out[(size_t)n * CLASSES + 2 * lane + 1] = o1 - mx - ls;
    }
}

// ---------------- launch: fork-join the edge pipeline beside GEMM1 -----------
extern "C" void kernel_launch(void* const* d_in, const int* in_sizes, int n_in,
                              void* d_out, int out_size) {
    const float* x    = (const float*)d_in[0];
    const void*  ei   = d_in[1];
    const float* W1   = (const float*)d_in[2];
    const float* asr1 = (const float*)d_in[3];
    const float* adt1 = (const float*)d_in[4];
    const float* b1   = (const float*)d_in[5];
    const float* W2   = (const float*)d_in[6];
    const float* asr2 = (const float*)d_in[7];
    const float* adt2 = (const float*)d_in[8];
    const float* b2   = (const float*)d_in[9];
    float* out = (float*)d_out;

    static cudaStream_t s_side = nullptr;
    static cudaEvent_t  s_fork = nullptr, s_join = nullptr;
    if (s_side == nullptr) {
        cudaStreamCreateWithFlags(&s_side, cudaStreamNonBlocking);
        cudaEventCreateWithFlags(&s_fork, cudaEventDisableTiming);
        cudaEventCreateWithFlags(&s_join, cudaEventDisableTiming);
    }

    cudaEventRecord(s_fork, 0);
    cudaStreamWaitEvent(s_side, s_fork, 0);

    prep_kernel<<<PREP_BLOCKS, 256, 0, s_side>>>((const long long*)ei);
    scatter_kernel<<<SCAT_BLOCKS, 256, 0, s_side>>>(ei);
    cudaEventRecord(s_join, s_side);

    kGemm1<<<GEMM1_TILES, 256>>>(x, W1, asr1, adt1);

    cudaStreamWaitEvent(0, s_join, 0);

    agg1_kernel<<<(N_NODES + 3) / 4, 128>>>(b1);
    gemm2_kernel<<<(N_NODES + 127) / 128, 256>>>(W2, asr2, adt2);
    agg2_kernel<<<(N_NODES + 7) / 8, 256>>>(b2, out);
}